// round 4
// baseline (speedup 1.0000x reference)
#include <cuda_runtime.h>
#include <math.h>

#define S_LEN  2048
#define D_MODEL 4096
#define NH     32
#define NKV    8
#define HD     128
#define QKDIM  (NH*HD)    // 4096
#define KVDIM  (NKV*HD)   // 1024
#define ATT_SCALE 0.08838834764831845f  // 1/sqrt(128)

// Scratch (device globals: allocation-free rule)
__device__ float g_q[S_LEN * QKDIM];
__device__ float g_k[S_LEN * KVDIM];
__device__ float g_v[S_LEN * KVDIM];
__device__ float g_ctx[S_LEN * QKDIM];

// ---------------------------------------------------------------------------
// Classic 128x128x8 SGEMM, 256 threads, 8x8 per-thread tile, with
// register-prefetch double buffering of the global tile loads.
// A [M,K] row-major, B [K,N] row-major, C [M,N] row-major.
// ---------------------------------------------------------------------------
__global__ __launch_bounds__(256) void sgemm_kernel(
    const float* __restrict__ A, const float* __restrict__ B,
    float* __restrict__ C, int M, int N, int K)
{
    __shared__ float As[8][128];
    __shared__ float Bs[8][128];
    const int tid = threadIdx.x;
    const int tx = tid & 15;          // 0..15 -> N sub-tile
    const int ty = tid >> 4;          // 0..15 -> M sub-tile
    const int aRow = tid >> 1;        // 0..127
    const int aCol = (tid & 1) * 4;   // 0 or 4
    const int bRow = tid >> 5;        // 0..7
    const int bCol = (tid & 31) * 4;  // 0..124

    const float* Ab = A + (size_t)blockIdx.y * 128 * K;
    const float* Bb = B + blockIdx.x * 128;

    float acc[8][8];
#pragma unroll
    for (int i = 0; i < 8; i++)
#pragma unroll
        for (int j = 0; j < 8; j++) acc[i][j] = 0.f;

    // prefetch first tile
    float4 a4 = *(const float4*)(Ab + (size_t)aRow * K + aCol);
    float4 b4 = *(const float4*)(Bb + (size_t)bRow * N + bCol);

    for (int k0 = 0; k0 < K; k0 += 8) {
        As[aCol + 0][aRow] = a4.x;
        As[aCol + 1][aRow] = a4.y;
        As[aCol + 2][aRow] = a4.z;
        As[aCol + 3][aRow] = a4.w;
        *(float4*)(&Bs[bRow][bCol]) = b4;
        __syncthreads();

        // prefetch next tile while computing this one
        if (k0 + 8 < K) {
            a4 = *(const float4*)(Ab + (size_t)aRow * K + k0 + 8 + aCol);
            b4 = *(const float4*)(Bb + (size_t)(k0 + 8 + bRow) * N + bCol);
        }

#pragma unroll
        for (int kk = 0; kk < 8; kk++) {
            float ar[8], br[8];
#pragma unroll
            for (int i = 0; i < 8; i++) ar[i] = As[kk][ty * 8 + i];
#pragma unroll
            for (int j = 0; j < 8; j++) br[j] = Bs[kk][tx * 8 + j];
#pragma unroll
            for (int i = 0; i < 8; i++)
#pragma unroll
                for (int j = 0; j < 8; j++)
                    acc[i][j] = fmaf(ar[i], br[j], acc[i][j]);
        }
        __syncthreads();
    }

    float* Cb = C + (size_t)(blockIdx.y * 128 + ty * 8) * N + blockIdx.x * 128 + tx * 8;
#pragma unroll
    for (int i = 0; i < 8; i++) {
        float4 v0 = make_float4(acc[i][0], acc[i][1], acc[i][2], acc[i][3]);
        float4 v1 = make_float4(acc[i][4], acc[i][5], acc[i][6], acc[i][7]);
        *(float4*)(Cb + (size_t)i * N + 0) = v0;
        *(float4*)(Cb + (size_t)i * N + 4) = v1;
    }
}

// ---------------------------------------------------------------------------
// RoPE, in place on Q and K. One block per sequence position.
// ---------------------------------------------------------------------------
__global__ void rope_kernel(float* __restrict__ Q, float* __restrict__ K,
                            const int* __restrict__ pos_ids)
{
    const int s = blockIdx.x;
    const float p = (float)pos_ids[s];
    const int total = (NH + NKV) * 64;
    for (int id = threadIdx.x; id < total; id += blockDim.x) {
        const int h = id >> 6;
        const int d = id & 63;
        const float freq = 1.0f / powf(1000000.0f, (float)d * (1.0f / 64.0f));
        const float t = p * freq;
        float sn, cs;
        sincosf(t, &sn, &cs);
        float* ptr;
        if (h < NH) ptr = Q + (size_t)s * QKDIM + h * HD;
        else        ptr = K + (size_t)s * KVDIM + (h - NH) * HD;
        const float x1 = ptr[d];
        const float x2 = ptr[d + 64];
        ptr[d]      = x1 * cs - x2 * sn;
        ptr[d + 64] = x1 * sn + x2 * cs;
    }
}

// ---------------------------------------------------------------------------
// Flash-style fp32 attention with smem-resident Q and K tiles (d-major).
// Grid: (S/64 q-blocks, NH heads). Block: 256 threads.
// Dynamic smem layout (floats):
//   Qall[128][64]   (d-major Q tile)      32 KB
//   Kall[128][64]   (d-major K tile)      32 KB
//   Ps  [64][65]    (probs, padded)       16.25 KB
//   Vs  [16][132]   (V chunk, padded)      8.25 KB
//   m_s[64], l_s[64], sc_s[64]             0.75 KB
// ---------------------------------------------------------------------------
#define ATTN_SMEM_FLOATS (128*64 + 128*64 + 64*65 + 16*132 + 3*64)
#define ATTN_SMEM_BYTES  (ATTN_SMEM_FLOATS * 4)

__global__ __launch_bounds__(256) void attn_kernel(
    const float* __restrict__ Q, const float* __restrict__ K,
    const float* __restrict__ V, const float* __restrict__ amask,
    float* __restrict__ ctx)
{
    extern __shared__ float sm[];
    float* Qall = sm;                       // [128][64]
    float* Kall = Qall + 128 * 64;          // [128][64]
    float* Ps   = Kall + 128 * 64;          // [64][65]
    float* Vs   = Ps   + 64 * 65;           // [16][132]
    float* m_s  = Vs   + 16 * 132;          // [64]
    float* l_s  = m_s  + 64;                // [64]
    float* sc_s = l_s  + 64;                // [64]

    const int tid = threadIdx.x;
    const int qb = blockIdx.x;
    const int h  = blockIdx.y;
    const int g  = h >> 2;           // kv head
    const int q0 = qb * 64;
    const int tx = tid & 15;         // 16 cols
    const int ty = tid >> 4;         // 16 rows

    float O[4][8];
#pragma unroll
    for (int r = 0; r < 4; r++)
#pragma unroll
        for (int c = 0; c < 8; c++) O[r][c] = 0.f;

    if (tid < 64) { m_s[tid] = -INFINITY; l_s[tid] = 0.f; }

    const int lm  = tid >> 2;        // 0..63  (row within tile)
    const int ld4 = (tid & 3) * 4;   // 0,4,8,12 (d sub-offset)

    // ---- load full Q tile once, transposed to d-major ----
#pragma unroll
    for (int d0 = 0; d0 < HD; d0 += 16) {
        float4 q4 = *(const float4*)(Q + (size_t)(q0 + lm) * QKDIM + h * HD + d0 + ld4);
        Qall[(d0 + ld4 + 0) * 64 + lm] = q4.x;
        Qall[(d0 + ld4 + 1) * 64 + lm] = q4.y;
        Qall[(d0 + ld4 + 2) * 64 + lm] = q4.z;
        Qall[(d0 + ld4 + 3) * 64 + lm] = q4.w;
    }
    __syncthreads();

    for (int kt = 0; kt <= qb; kt++) {
        const int k0 = kt * 64;

        // ---- load full K tile, transposed to d-major ----
#pragma unroll
        for (int d0 = 0; d0 < HD; d0 += 16) {
            float4 k4 = *(const float4*)(K + (size_t)(k0 + lm) * KVDIM + g * HD + d0 + ld4);
            Kall[(d0 + ld4 + 0) * 64 + lm] = k4.x;
            Kall[(d0 + ld4 + 1) * 64 + lm] = k4.y;
            Kall[(d0 + ld4 + 2) * 64 + lm] = k4.z;
            Kall[(d0 + ld4 + 3) * 64 + lm] = k4.w;
        }
        __syncthreads();

        // ---- S = (Q @ K^T) * scale : one pass, no barriers ----
        float s[4][4];
#pragma unroll
        for (int i = 0; i < 4; i++)
#pragma unroll
            for (int j = 0; j < 4; j++) s[i][j] = 0.f;

#pragma unroll 8
        for (int dd = 0; dd < HD; dd++) {
            float4 qa = *(const float4*)(&Qall[dd * 64 + ty * 4]);
            float4 kb = *(const float4*)(&Kall[dd * 64 + tx * 4]);
            s[0][0] = fmaf(qa.x, kb.x, s[0][0]);
            s[0][1] = fmaf(qa.x, kb.y, s[0][1]);
            s[0][2] = fmaf(qa.x, kb.z, s[0][2]);
            s[0][3] = fmaf(qa.x, kb.w, s[0][3]);
            s[1][0] = fmaf(qa.y, kb.x, s[1][0]);
            s[1][1] = fmaf(qa.y, kb.y, s[1][1]);
            s[1][2] = fmaf(qa.y, kb.z, s[1][2]);
            s[1][3] = fmaf(qa.y, kb.w, s[1][3]);
            s[2][0] = fmaf(qa.z, kb.x, s[2][0]);
            s[2][1] = fmaf(qa.z, kb.y, s[2][1]);
            s[2][2] = fmaf(qa.z, kb.z, s[2][2]);
            s[2][3] = fmaf(qa.z, kb.w, s[2][3]);
            s[3][0] = fmaf(qa.w, kb.x, s[3][0]);
            s[3][1] = fmaf(qa.w, kb.y, s[3][1]);
            s[3][2] = fmaf(qa.w, kb.z, s[3][2]);
            s[3][3] = fmaf(qa.w, kb.w, s[3][3]);
        }
#pragma unroll
        for (int i = 0; i < 4; i++)
#pragma unroll
            for (int j = 0; j < 4; j++)
                Ps[(ty * 4 + i) * 65 + tx * 4 + j] = s[i][j] * ATT_SCALE;
        __syncthreads();

        // ---- online softmax update (4 threads per row, 16 cols each) ----
        {
            const int row = tid >> 2;
            const int sub = tid & 3;
            const int qg  = q0 + row;
            float pv[16];
            float mloc = -INFINITY;
#pragma unroll
            for (int c2 = 0; c2 < 16; c2++) {
                const int kk = sub * 16 + c2;
                const int kg = k0 + kk;
                float sv = Ps[row * 65 + kk];
                if (kg > qg || amask[kg] <= 0.f) sv = -INFINITY;
                pv[c2] = sv;
                mloc = fmaxf(mloc, sv);
            }
            mloc = fmaxf(mloc, __shfl_xor_sync(0xffffffffu, mloc, 1));
            mloc = fmaxf(mloc, __shfl_xor_sync(0xffffffffu, mloc, 2));
            const float mold = m_s[row];
            const float mnew = fmaxf(mold, mloc);
            float lsum = 0.f;
#pragma unroll
            for (int c2 = 0; c2 < 16; c2++) {
                const float pexp = expf(pv[c2] - mnew);  // -inf -> 0
                Ps[row * 65 + sub * 16 + c2] = pexp;
                lsum += pexp;
            }
            lsum += __shfl_xor_sync(0xffffffffu, lsum, 1);
            lsum += __shfl_xor_sync(0xffffffffu, lsum, 2);
            if (sub == 0) {
                const float f = expf(mold - mnew);
                sc_s[row] = f;
                l_s[row]  = l_s[row] * f + lsum;
                m_s[row]  = mnew;
            }
        }
        __syncthreads();

        // ---- O = O*f + P @ V ----
#pragma unroll
        for (int r = 0; r < 4; r++) {
            const float f = sc_s[ty * 4 + r];
#pragma unroll
            for (int c = 0; c < 8; c++) O[r][c] *= f;
        }
        for (int kk0 = 0; kk0 < 64; kk0 += 16) {
            __syncthreads();
#pragma unroll
            for (int t2 = 0; t2 < 2; t2++) {
                const int idx = tid + t2 * 256;
                const int vr = idx >> 5;
                const int vc = (idx & 31) * 4;
                *(float4*)(&Vs[vr * 132 + vc]) =
                    *(const float4*)(V + (size_t)(k0 + kk0 + vr) * KVDIM + g * HD + vc);
            }
            __syncthreads();
#pragma unroll
            for (int kk = 0; kk < 16; kk++) {
                float pr[4], vv[8];
#pragma unroll
                for (int r = 0; r < 4; r++) pr[r] = Ps[(ty * 4 + r) * 65 + kk0 + kk];
#pragma unroll
                for (int c = 0; c < 8; c++) vv[c] = Vs[kk * 132 + tx * 8 + c];
#pragma unroll
                for (int r = 0; r < 4; r++)
#pragma unroll
                    for (int c = 0; c < 8; c++)
                        O[r][c] = fmaf(pr[r], vv[c], O[r][c]);
            }
        }
        __syncthreads();
    }

    // ---- epilogue: normalize and write ctx ----
#pragma unroll
    for (int r = 0; r < 4; r++) {
        const float inv = 1.0f / l_s[ty * 4 + r];
        float* dst = ctx + (size_t)(q0 + ty * 4 + r) * QKDIM + h * HD + tx * 8;
        float4 v0 = make_float4(O[r][0] * inv, O[r][1] * inv, O[r][2] * inv, O[r][3] * inv);
        float4 v1 = make_float4(O[r][4] * inv, O[r][5] * inv, O[r][6] * inv, O[r][7] * inv);
        *(float4*)(dst + 0) = v0;
        *(float4*)(dst + 4) = v1;
    }
}

// ---------------------------------------------------------------------------
extern "C" void kernel_launch(void* const* d_in, const int* in_sizes, int n_in,
                              void* d_out, int out_size)
{
    const float* hidden = (const float*)d_in[0];
    const float* amask  = (const float*)d_in[1];
    const int*   pos    = (const int*)d_in[2];
    const float* wq     = (const float*)d_in[3];
    const float* wk     = (const float*)d_in[4];
    const float* wv     = (const float*)d_in[5];
    const float* wo     = (const float*)d_in[6];
    float* out = (float*)d_out;

    float *qp, *kp, *vp, *cp;
    cudaGetSymbolAddress((void**)&qp, g_q);
    cudaGetSymbolAddress((void**)&kp, g_k);
    cudaGetSymbolAddress((void**)&vp, g_v);
    cudaGetSymbolAddress((void**)&cp, g_ctx);

    cudaFuncSetAttribute(attn_kernel,
                         cudaFuncAttributeMaxDynamicSharedMemorySize,
                         ATTN_SMEM_BYTES);

    dim3 blk(256);
    // QKV projections
    sgemm_kernel<<<dim3(QKDIM / 128, S_LEN / 128), blk>>>(hidden, wq, qp, S_LEN, QKDIM, D_MODEL);
    sgemm_kernel<<<dim3(KVDIM / 128, S_LEN / 128), blk>>>(hidden, wk, kp, S_LEN, KVDIM, D_MODEL);
    sgemm_kernel<<<dim3(KVDIM / 128, S_LEN / 128), blk>>>(hidden, wv, vp, S_LEN, KVDIM, D_MODEL);
    // RoPE (in place on Q, K)
    rope_kernel<<<S_LEN, 256>>>(qp, kp, pos);
    // Attention
    attn_kernel<<<dim3(S_LEN / 64, NH), blk, ATTN_SMEM_BYTES>>>(qp, kp, vp, amask, cp);
    // Output projection
    sgemm_kernel<<<dim3(QKDIM / 128, S_LEN / 128), blk>>>(cp, wo, out, S_LEN, QKDIM, D_MODEL);
}

// round 6
// speedup vs baseline: 1.3595x; 1.3595x over previous
#include <cuda_runtime.h>
#include <cuda_bf16.h>
#include <math.h>
#include <stdint.h>

#define S_LEN  2048
#define D_MODEL 4096
#define NH     32
#define NKV    8
#define HD     128
#define QKDIM  (NH*HD)    // 4096
#define KVDIM  (NKV*HD)   // 1024
#define K3     (3*D_MODEL)  // 12288 : split-interleaved K
#define ATT_SCALE 0.08838834764831845f  // 1/sqrt(128)

// Scratch (device globals: allocation-free rule)
__device__ float g_q[S_LEN * QKDIM];
__device__ float g_k[S_LEN * KVDIM];
__device__ float g_v[S_LEN * KVDIM];
__device__ float g_ctx[S_LEN * QKDIM];
__device__ __nv_bfloat16 g_h3[S_LEN * K3];        // split A operand (hidden / ctx)
__device__ __nv_bfloat16 g_w3[(size_t)K3 * QKDIM]; // split B operand (one weight at a time)

// ---------------------------------------------------------------------------
// Split-precision conversion.
// Each fp32 x -> hi = bf16(x), lo = bf16(x - hi).
// A pattern (per k, along K): (hi, lo, hi)
// B pattern (per k, row-replicated): row 3k = hi, row 3k+1 = hi, row 3k+2 = lo
// Dot over K'=3K gives hi*hi + lo*hi + hi*lo  ~= full fp32 product.
// ---------------------------------------------------------------------------
__global__ void split3_a_kernel(const float* __restrict__ X,
                                __nv_bfloat16* __restrict__ Y, int nblk8)
{
    int t = blockIdx.x * blockDim.x + threadIdx.x;
    if (t >= nblk8) return;
    size_t e = (size_t)t * 8;
    float4 x0 = *(const float4*)(X + e);
    float4 x1 = *(const float4*)(X + e + 4);
    float xs[8] = {x0.x, x0.y, x0.z, x0.w, x1.x, x1.y, x1.z, x1.w};
    __nv_bfloat16 out[24];
#pragma unroll
    for (int j = 0; j < 8; j++) {
        __nv_bfloat16 hi = __float2bfloat16(xs[j]);
        __nv_bfloat16 lo = __float2bfloat16(xs[j] - __bfloat162float(hi));
        out[3 * j + 0] = hi;
        out[3 * j + 1] = lo;
        out[3 * j + 2] = hi;
    }
    uint4* dst = (uint4*)(Y + 3 * e);
    const uint4* src = (const uint4*)out;
    dst[0] = src[0]; dst[1] = src[1]; dst[2] = src[2];
}

__global__ void split3_b_kernel(const float* __restrict__ W,
                                __nv_bfloat16* __restrict__ Y, int K, int N)
{
    int t = blockIdx.x * blockDim.x + threadIdx.x;
    int per_row = N >> 3;
    if (t >= K * per_row) return;
    int k  = t / per_row;
    int n0 = (t - k * per_row) << 3;
    float4 x0 = *(const float4*)(W + (size_t)k * N + n0);
    float4 x1 = *(const float4*)(W + (size_t)k * N + n0 + 4);
    float xs[8] = {x0.x, x0.y, x0.z, x0.w, x1.x, x1.y, x1.z, x1.w};
    __nv_bfloat16 hi[8], lo[8];
#pragma unroll
    for (int j = 0; j < 8; j++) {
        hi[j] = __float2bfloat16(xs[j]);
        lo[j] = __float2bfloat16(xs[j] - __bfloat162float(hi[j]));
    }
    uint4 hv = *(const uint4*)hi;
    uint4 lv = *(const uint4*)lo;
    *(uint4*)(Y + (size_t)(3 * k + 0) * N + n0) = hv;
    *(uint4*)(Y + (size_t)(3 * k + 1) * N + n0) = hv;
    *(uint4*)(Y + (size_t)(3 * k + 2) * N + n0) = lv;
}

// ---------------------------------------------------------------------------
// bf16 tensor-core GEMM: C[M][N] = A[M][K3] * B[K3][N], fp32 accumulate.
// CTA tile 128x128, 8 warps (4M x 2N), mma.sync.m16n8k16, K-step 32.
// Smem rows padded (A:40, B:136 bf16) => conflict-free ldmatrix.
// ---------------------------------------------------------------------------
#define LDMX4(r0, r1, r2, r3, addr) \
    asm volatile("ldmatrix.sync.aligned.m8n8.x4.shared.b16 {%0,%1,%2,%3}, [%4];" \
                 : "=r"(r0), "=r"(r1), "=r"(r2), "=r"(r3) : "r"(addr))
#define LDMX4T(r0, r1, r2, r3, addr) \
    asm volatile("ldmatrix.sync.aligned.m8n8.x4.trans.shared.b16 {%0,%1,%2,%3}, [%4];" \
                 : "=r"(r0), "=r"(r1), "=r"(r2), "=r"(r3) : "r"(addr))
#define MMA16816(d, a, b0, b1) \
    asm volatile("mma.sync.aligned.m16n8k16.row.col.f32.bf16.bf16.f32 " \
                 "{%0,%1,%2,%3},{%4,%5,%6,%7},{%8,%9},{%0,%1,%2,%3};" \
                 : "+f"(d[0]), "+f"(d[1]), "+f"(d[2]), "+f"(d[3]) \
                 : "r"(a[0]), "r"(a[1]), "r"(a[2]), "r"(a[3]), "r"(b0), "r"(b1))

__global__ __launch_bounds__(256) void bf16_gemm_kernel(
    const __nv_bfloat16* __restrict__ A, const __nv_bfloat16* __restrict__ B,
    float* __restrict__ C, int N)
{
    __shared__ __nv_bfloat16 As[128 * 40];   // [row][k] padded
    __shared__ __nv_bfloat16 Bs[32 * 136];   // [k][n] padded

    const int tid  = threadIdx.x;
    const int wid  = tid >> 5;
    const int lane = tid & 31;
    const int wm   = wid >> 1;   // 0..3 -> M offset wm*32
    const int wn   = wid & 1;    // 0..1 -> N offset wn*64

    const int m0 = blockIdx.y * 128;
    const int n0 = blockIdx.x * 128;

    // global load mapping
    const int arow = tid >> 1;          // 0..127
    const int acol = (tid & 1) * 16;    // 0 or 16
    const int brow = tid >> 3;          // 0..31
    const int bcol = (tid & 7) * 16;    // 0..112

    const __nv_bfloat16* Ag = A + (size_t)(m0 + arow) * K3 + acol;
    const __nv_bfloat16* Bg = B + (size_t)brow * N + n0 + bcol;

    float acc[2][8][4];
#pragma unroll
    for (int mt = 0; mt < 2; mt++)
#pragma unroll
        for (int nt = 0; nt < 8; nt++)
#pragma unroll
            for (int i = 0; i < 4; i++) acc[mt][nt][i] = 0.f;

    const uint32_t a_base = (uint32_t)__cvta_generic_to_shared(As);
    const uint32_t b_base = (uint32_t)__cvta_generic_to_shared(Bs);
    // ldmatrix per-lane addresses (same formula for A and B-trans)
    const uint32_t a_lane_off = (uint32_t)(((lane & 15) * 40 + (lane >> 4) * 8) * 2);
    const uint32_t b_lane_off = (uint32_t)(((lane & 15) * 136 + (lane >> 4) * 8) * 2);

    // prefetch first tile
    uint4 pa0 = *(const uint4*)(Ag);
    uint4 pa1 = *(const uint4*)(Ag + 8);
    uint4 pb0 = *(const uint4*)(Bg);
    uint4 pb1 = *(const uint4*)(Bg + 8);

    const int ntile = K3 / 32;
    for (int kt = 0; kt < ntile; kt++) {
        *(uint4*)(As + arow * 40 + acol)     = pa0;
        *(uint4*)(As + arow * 40 + acol + 8) = pa1;
        *(uint4*)(Bs + brow * 136 + bcol)     = pb0;
        *(uint4*)(Bs + brow * 136 + bcol + 8) = pb1;
        __syncthreads();

        if (kt + 1 < ntile) {
            const __nv_bfloat16* An = Ag + (kt + 1) * 32;
            const __nv_bfloat16* Bn = Bg + (size_t)(kt + 1) * 32 * N;
            pa0 = *(const uint4*)(An);
            pa1 = *(const uint4*)(An + 8);
            pb0 = *(const uint4*)(Bn);
            pb1 = *(const uint4*)(Bn + 8);
        }

#pragma unroll
        for (int ks = 0; ks < 2; ks++) {
            const int kk = ks * 16;
            uint32_t af[2][4];
#pragma unroll
            for (int mt = 0; mt < 2; mt++) {
                uint32_t addr = a_base + a_lane_off +
                                (uint32_t)(((wm * 32 + mt * 16) * 40 + kk) * 2);
                LDMX4(af[mt][0], af[mt][1], af[mt][2], af[mt][3], addr);
            }
            uint32_t bf[4][4];
#pragma unroll
            for (int bt = 0; bt < 4; bt++) {
                uint32_t addr = b_base + b_lane_off +
                                (uint32_t)((kk * 136 + wn * 64 + bt * 16) * 2);
                LDMX4T(bf[bt][0], bf[bt][1], bf[bt][2], bf[bt][3], addr);
            }
#pragma unroll
            for (int mt = 0; mt < 2; mt++)
#pragma unroll
                for (int nt = 0; nt < 8; nt++) {
                    const int bt = nt >> 1, hf = nt & 1;
                    MMA16816(acc[mt][nt], af[mt], bf[bt][hf * 2], bf[bt][hf * 2 + 1]);
                }
        }
        __syncthreads();
    }

    // epilogue
#pragma unroll
    for (int mt = 0; mt < 2; mt++)
#pragma unroll
        for (int nt = 0; nt < 8; nt++) {
            const int m = m0 + wm * 32 + mt * 16 + (lane >> 2);
            const int n = n0 + wn * 64 + nt * 8 + (lane & 3) * 2;
            *(float2*)(C + (size_t)m * N + n) =
                make_float2(acc[mt][nt][0], acc[mt][nt][1]);
            *(float2*)(C + (size_t)(m + 8) * N + n) =
                make_float2(acc[mt][nt][2], acc[mt][nt][3]);
        }
}

// ---------------------------------------------------------------------------
// RoPE, in place on Q and K. One block per sequence position.
// ---------------------------------------------------------------------------
__global__ void rope_kernel(float* __restrict__ Q, float* __restrict__ K,
                            const int* __restrict__ pos_ids)
{
    const int s = blockIdx.x;
    const float p = (float)pos_ids[s];
    const int total = (NH + NKV) * 64;
    for (int id = threadIdx.x; id < total; id += blockDim.x) {
        const int h = id >> 6;
        const int d = id & 63;
        const float freq = 1.0f / powf(1000000.0f, (float)d * (1.0f / 64.0f));
        const float t = p * freq;
        float sn, cs;
        sincosf(t, &sn, &cs);
        float* ptr;
        if (h < NH) ptr = Q + (size_t)s * QKDIM + h * HD;
        else        ptr = K + (size_t)s * KVDIM + (h - NH) * HD;
        const float x1 = ptr[d];
        const float x2 = ptr[d + 64];
        ptr[d]      = x1 * cs - x2 * sn;
        ptr[d + 64] = x1 * sn + x2 * cs;
    }
}

// ---------------------------------------------------------------------------
// Flash-style fp32 attention with smem-resident Q and K tiles (d-major).
// Grid: (S/64 q-blocks, NH heads). Block: 256 threads.  (unchanged, passing)
// ---------------------------------------------------------------------------
#define ATTN_SMEM_FLOATS (128*64 + 128*64 + 64*65 + 16*132 + 3*64)
#define ATTN_SMEM_BYTES  (ATTN_SMEM_FLOATS * 4)

__global__ __launch_bounds__(256) void attn_kernel(
    const float* __restrict__ Q, const float* __restrict__ K,
    const float* __restrict__ V, const float* __restrict__ amask,
    float* __restrict__ ctx)
{
    extern __shared__ float sm[];
    float* Qall = sm;                       // [128][64]
    float* Kall = Qall + 128 * 64;          // [128][64]
    float* Ps   = Kall + 128 * 64;          // [64][65]
    float* Vs   = Ps   + 64 * 65;           // [16][132]
    float* m_s  = Vs   + 16 * 132;          // [64]
    float* l_s  = m_s  + 64;                // [64]
    float* sc_s = l_s  + 64;                // [64]

    const int tid = threadIdx.x;
    const int qb = blockIdx.x;
    const int h  = blockIdx.y;
    const int g  = h >> 2;           // kv head
    const int q0 = qb * 64;
    const int tx = tid & 15;         // 16 cols
    const int ty = tid >> 4;         // 16 rows

    float O[4][8];
#pragma unroll
    for (int r = 0; r < 4; r++)
#pragma unroll
        for (int c = 0; c < 8; c++) O[r][c] = 0.f;

    if (tid < 64) { m_s[tid] = -INFINITY; l_s[tid] = 0.f; }

    const int lm  = tid >> 2;        // 0..63  (row within tile)
    const int ld4 = (tid & 3) * 4;   // 0,4,8,12 (d sub-offset)

    // ---- load full Q tile once, transposed to d-major ----
#pragma unroll
    for (int d0 = 0; d0 < HD; d0 += 16) {
        float4 q4 = *(const float4*)(Q + (size_t)(q0 + lm) * QKDIM + h * HD + d0 + ld4);
        Qall[(d0 + ld4 + 0) * 64 + lm] = q4.x;
        Qall[(d0 + ld4 + 1) * 64 + lm] = q4.y;
        Qall[(d0 + ld4 + 2) * 64 + lm] = q4.z;
        Qall[(d0 + ld4 + 3) * 64 + lm] = q4.w;
    }
    __syncthreads();

    for (int kt = 0; kt <= qb; kt++) {
        const int k0 = kt * 64;

#pragma unroll
        for (int d0 = 0; d0 < HD; d0 += 16) {
            float4 k4 = *(const float4*)(K + (size_t)(k0 + lm) * KVDIM + g * HD + d0 + ld4);
            Kall[(d0 + ld4 + 0) * 64 + lm] = k4.x;
            Kall[(d0 + ld4 + 1) * 64 + lm] = k4.y;
            Kall[(d0 + ld4 + 2) * 64 + lm] = k4.z;
            Kall[(d0 + ld4 + 3) * 64 + lm] = k4.w;
        }
        __syncthreads();

        float s[4][4];
#pragma unroll
        for (int i = 0; i < 4; i++)
#pragma unroll
            for (int j = 0; j < 4; j++) s[i][j] = 0.f;

#pragma unroll 8
        for (int dd = 0; dd < HD; dd++) {
            float4 qa = *(const float4*)(&Qall[dd * 64 + ty * 4]);
            float4 kb = *(const float4*)(&Kall[dd * 64 + tx * 4]);
            s[0][0] = fmaf(qa.x, kb.x, s[0][0]);
            s[0][1] = fmaf(qa.x, kb.y, s[0][1]);
            s[0][2] = fmaf(qa.x, kb.z, s[0][2]);
            s[0][3] = fmaf(qa.x, kb.w, s[0][3]);
            s[1][0] = fmaf(qa.y, kb.x, s[1][0]);
            s[1][1] = fmaf(qa.y, kb.y, s[1][1]);
            s[1][2] = fmaf(qa.y, kb.z, s[1][2]);
            s[1][3] = fmaf(qa.y, kb.w, s[1][3]);
            s[2][0] = fmaf(qa.z, kb.x, s[2][0]);
            s[2][1] = fmaf(qa.z, kb.y, s[2][1]);
            s[2][2] = fmaf(qa.z, kb.z, s[2][2]);
            s[2][3] = fmaf(qa.z, kb.w, s[2][3]);
            s[3][0] = fmaf(qa.w, kb.x, s[3][0]);
            s[3][1] = fmaf(qa.w, kb.y, s[3][1]);
            s[3][2] = fmaf(qa.w, kb.z, s[3][2]);
            s[3][3] = fmaf(qa.w, kb.w, s[3][3]);
        }
#pragma unroll
        for (int i = 0; i < 4; i++)
#pragma unroll
            for (int j = 0; j < 4; j++)
                Ps[(ty * 4 + i) * 65 + tx * 4 + j] = s[i][j] * ATT_SCALE;
        __syncthreads();

        {
            const int row = tid >> 2;
            const int sub = tid & 3;
            const int qg  = q0 + row;
            float pv[16];
            float mloc = -INFINITY;
#pragma unroll
            for (int c2 = 0; c2 < 16; c2++) {
                const int kk = sub * 16 + c2;
                const int kg = k0 + kk;
                float sv = Ps[row * 65 + kk];
                if (kg > qg || amask[kg] <= 0.f) sv = -INFINITY;
                pv[c2] = sv;
                mloc = fmaxf(mloc, sv);
            }
            mloc = fmaxf(mloc, __shfl_xor_sync(0xffffffffu, mloc, 1));
            mloc = fmaxf(mloc, __shfl_xor_sync(0xffffffffu, mloc, 2));
            const float mold = m_s[row];
            const float mnew = fmaxf(mold, mloc);
            float lsum = 0.f;
#pragma unroll
            for (int c2 = 0; c2 < 16; c2++) {
                const float pexp = expf(pv[c2] - mnew);
                Ps[row * 65 + sub * 16 + c2] = pexp;
                lsum += pexp;
            }
            lsum += __shfl_xor_sync(0xffffffffu, lsum, 1);
            lsum += __shfl_xor_sync(0xffffffffu, lsum, 2);
            if (sub == 0) {
                const float f = expf(mold - mnew);
                sc_s[row] = f;
                l_s[row]  = l_s[row] * f + lsum;
                m_s[row]  = mnew;
            }
        }
        __syncthreads();

#pragma unroll
        for (int r = 0; r < 4; r++) {
            const float f = sc_s[ty * 4 + r];
#pragma unroll
            for (int c = 0; c < 8; c++) O[r][c] *= f;
        }
        for (int kk0 = 0; kk0 < 64; kk0 += 16) {
            __syncthreads();
#pragma unroll
            for (int t2 = 0; t2 < 2; t2++) {
                const int idx = tid + t2 * 256;
                const int vr = idx >> 5;
                const int vc = (idx & 31) * 4;
                *(float4*)(&Vs[vr * 132 + vc]) =
                    *(const float4*)(V + (size_t)(k0 + kk0 + vr) * KVDIM + g * HD + vc);
            }
            __syncthreads();
#pragma unroll
            for (int kk = 0; kk < 16; kk++) {
                float pr[4], vv[8];
#pragma unroll
                for (int r = 0; r < 4; r++) pr[r] = Ps[(ty * 4 + r) * 65 + kk0 + kk];
#pragma unroll
                for (int c = 0; c < 8; c++) vv[c] = Vs[kk * 132 + tx * 8 + c];
#pragma unroll
                for (int r = 0; r < 4; r++)
#pragma unroll
                    for (int c = 0; c < 8; c++)
                        O[r][c] = fmaf(pr[r], vv[c], O[r][c]);
            }
        }
        __syncthreads();
    }

#pragma unroll
    for (int r = 0; r < 4; r++) {
        const float inv = 1.0f / l_s[ty * 4 + r];
        float* dst = ctx + (size_t)(q0 + ty * 4 + r) * QKDIM + h * HD + tx * 8;
        float4 v0 = make_float4(O[r][0] * inv, O[r][1] * inv, O[r][2] * inv, O[r][3] * inv);
        float4 v1 = make_float4(O[r][4] * inv, O[r][5] * inv, O[r][6] * inv, O[r][7] * inv);
        *(float4*)(dst + 0) = v0;
        *(float4*)(dst + 4) = v1;
    }
}

// ---------------------------------------------------------------------------
extern "C" void kernel_launch(void* const* d_in, const int* in_sizes, int n_in,
                              void* d_out, int out_size)
{
    const float* hidden = (const float*)d_in[0];
    const float* amask  = (const float*)d_in[1];
    const int*   pos    = (const int*)d_in[2];
    const float* wq     = (const float*)d_in[3];
    const float* wk     = (const float*)d_in[4];
    const float* wv     = (const float*)d_in[5];
    const float* wo     = (const float*)d_in[6];
    float* out = (float*)d_out;

    float *qp, *kp, *vp, *cp;
    __nv_bfloat16 *h3, *w3;
    cudaGetSymbolAddress((void**)&qp, g_q);
    cudaGetSymbolAddress((void**)&kp, g_k);
    cudaGetSymbolAddress((void**)&vp, g_v);
    cudaGetSymbolAddress((void**)&cp, g_ctx);
    cudaGetSymbolAddress((void**)&h3, g_h3);
    cudaGetSymbolAddress((void**)&w3, g_w3);

    cudaFuncSetAttribute(attn_kernel,
                         cudaFuncAttributeMaxDynamicSharedMemorySize,
                         ATTN_SMEM_BYTES);

    const int na = S_LEN * D_MODEL / 8;                    // A-side 8-elem blocks
    // hidden -> split A operand
    split3_a_kernel<<<(na + 255) / 256, 256>>>(hidden, h3, na);

    // Q = h3 * wq'
    split3_b_kernel<<<(D_MODEL * (QKDIM / 8) + 255) / 256, 256>>>(wq, w3, D_MODEL, QKDIM);
    bf16_gemm_kernel<<<dim3(QKDIM / 128, S_LEN / 128), 256>>>(h3, w3, qp, QKDIM);
    // K = h3 * wk'
    split3_b_kernel<<<(D_MODEL * (KVDIM / 8) + 255) / 256, 256>>>(wk, w3, D_MODEL, KVDIM);
    bf16_gemm_kernel<<<dim3(KVDIM / 128, S_LEN / 128), 256>>>(h3, w3, kp, KVDIM);
    // V = h3 * wv'
    split3_b_kernel<<<(D_MODEL * (KVDIM / 8) + 255) / 256, 256>>>(wv, w3, D_MODEL, KVDIM);
    bf16_gemm_kernel<<<dim3(KVDIM / 128, S_LEN / 128), 256>>>(h3, w3, vp, KVDIM);

    // RoPE (in place on Q, K)
    rope_kernel<<<S_LEN, 256>>>(qp, kp, pos);
    // Attention
    attn_kernel<<<dim3(S_LEN / 64, NH), 256, ATTN_SMEM_BYTES>>>(qp, kp, vp, amask, cp);

    // out = ctx' * wo'
    split3_a_kernel<<<(na + 255) / 256, 256>>>(cp, h3, na);
    split3_b_kernel<<<(D_MODEL * (QKDIM / 8) + 255) / 256, 256>>>(wo, w3, D_MODEL, QKDIM);
    bf16_gemm_kernel<<<dim3(QKDIM / 128, S_LEN / 128), 256>>>(h3, w3, out, QKDIM);
}

// round 7
// speedup vs baseline: 1.7716x; 1.3032x over previous
#include <cuda_runtime.h>
#include <cuda_bf16.h>
#include <math.h>
#include <stdint.h>

#define S_LEN  2048
#define D_MODEL 4096
#define NH     32
#define NKV    8
#define HD     128
#define QKDIM  (NH*HD)    // 4096
#define KVDIM  (NKV*HD)   // 1024
#define K3     (3*D_MODEL)  // 12288 : split-interleaved K
#define ATT_SCALE 0.08838834764831845f  // 1/sqrt(128)

// Scratch (device globals: allocation-free rule)
__device__ float g_q[S_LEN * QKDIM];
__device__ float g_k[S_LEN * KVDIM];
__device__ float g_v[S_LEN * KVDIM];
__device__ float g_ctx[S_LEN * QKDIM];
__device__ __nv_bfloat16 g_h3[S_LEN * K3];        // split A operand (hidden / ctx)
__device__ __nv_bfloat16 g_w3[(size_t)K3 * QKDIM]; // split B operand (one weight at a time)

// ---------------------------------------------------------------------------
// Split-precision conversion.
// Each fp32 x -> hi = bf16(x), lo = bf16(x - hi).
// A pattern (per k, along K): (hi, lo, hi)
// B pattern (per k, row-replicated): row 3k = hi, row 3k+1 = hi, row 3k+2 = lo
// Dot over K'=3K gives hi*hi + lo*hi + hi*lo  ~= full fp32 product.
// ---------------------------------------------------------------------------
__global__ void split3_a_kernel(const float* __restrict__ X,
                                __nv_bfloat16* __restrict__ Y, int nblk8)
{
    int t = blockIdx.x * blockDim.x + threadIdx.x;
    if (t >= nblk8) return;
    size_t e = (size_t)t * 8;
    float4 x0 = *(const float4*)(X + e);
    float4 x1 = *(const float4*)(X + e + 4);
    float xs[8] = {x0.x, x0.y, x0.z, x0.w, x1.x, x1.y, x1.z, x1.w};
    __nv_bfloat16 out[24];
#pragma unroll
    for (int j = 0; j < 8; j++) {
        __nv_bfloat16 hi = __float2bfloat16(xs[j]);
        __nv_bfloat16 lo = __float2bfloat16(xs[j] - __bfloat162float(hi));
        out[3 * j + 0] = hi;
        out[3 * j + 1] = lo;
        out[3 * j + 2] = hi;
    }
    uint4* dst = (uint4*)(Y + 3 * e);
    const uint4* src = (const uint4*)out;
    dst[0] = src[0]; dst[1] = src[1]; dst[2] = src[2];
}

__global__ void split3_b_kernel(const float* __restrict__ W,
                                __nv_bfloat16* __restrict__ Y, int K, int N)
{
    int t = blockIdx.x * blockDim.x + threadIdx.x;
    int per_row = N >> 3;
    if (t >= K * per_row) return;
    int k  = t / per_row;
    int n0 = (t - k * per_row) << 3;
    float4 x0 = *(const float4*)(W + (size_t)k * N + n0);
    float4 x1 = *(const float4*)(W + (size_t)k * N + n0 + 4);
    float xs[8] = {x0.x, x0.y, x0.z, x0.w, x1.x, x1.y, x1.z, x1.w};
    __nv_bfloat16 hi[8], lo[8];
#pragma unroll
    for (int j = 0; j < 8; j++) {
        hi[j] = __float2bfloat16(xs[j]);
        lo[j] = __float2bfloat16(xs[j] - __bfloat162float(hi[j]));
    }
    uint4 hv = *(const uint4*)hi;
    uint4 lv = *(const uint4*)lo;
    *(uint4*)(Y + (size_t)(3 * k + 0) * N + n0) = hv;
    *(uint4*)(Y + (size_t)(3 * k + 1) * N + n0) = hv;
    *(uint4*)(Y + (size_t)(3 * k + 2) * N + n0) = lv;
}

// ---------------------------------------------------------------------------
// bf16 tensor-core GEMM: C[M][N] = A[M][K3] * B[K3][N], fp32 accumulate.
// CTA tile 128x128, 8 warps (4M x 2N), mma.sync.m16n8k16, K-step 32.
// 4-stage cp.async smem pipeline, one __syncthreads per K-tile.
// Smem rows padded (A:40, B:136 bf16) => conflict-free ldmatrix.
// ---------------------------------------------------------------------------
#define LDMX4(r0, r1, r2, r3, addr) \
    asm volatile("ldmatrix.sync.aligned.m8n8.x4.shared.b16 {%0,%1,%2,%3}, [%4];" \
                 : "=r"(r0), "=r"(r1), "=r"(r2), "=r"(r3) : "r"(addr))
#define LDMX4T(r0, r1, r2, r3, addr) \
    asm volatile("ldmatrix.sync.aligned.m8n8.x4.trans.shared.b16 {%0,%1,%2,%3}, [%4];" \
                 : "=r"(r0), "=r"(r1), "=r"(r2), "=r"(r3) : "r"(addr))
#define MMA16816(d, a, b0, b1) \
    asm volatile("mma.sync.aligned.m16n8k16.row.col.f32.bf16.bf16.f32 " \
                 "{%0,%1,%2,%3},{%4,%5,%6,%7},{%8,%9},{%0,%1,%2,%3};" \
                 : "+f"(d[0]), "+f"(d[1]), "+f"(d[2]), "+f"(d[3]) \
                 : "r"(a[0]), "r"(a[1]), "r"(a[2]), "r"(a[3]), "r"(b0), "r"(b1))
#define CPASYNC16(dst, src) \
    asm volatile("cp.async.cg.shared.global [%0], [%1], 16;" :: "r"(dst), "l"(src))
#define CPCOMMIT() asm volatile("cp.async.commit_group;" ::: "memory")
#define CPWAIT2()  asm volatile("cp.async.wait_group 2;" ::: "memory")

#define GSTAGES   4
#define A_STG     (128 * 40)          // bf16 elems per A stage
#define B_STG     (32 * 136)          // bf16 elems per B stage
#define GEMM_SMEM_BYTES ((GSTAGES * (A_STG + B_STG)) * 2)

__global__ __launch_bounds__(256) void bf16_gemm_kernel(
    const __nv_bfloat16* __restrict__ A, const __nv_bfloat16* __restrict__ B,
    float* __restrict__ C, int N)
{
    extern __shared__ __nv_bfloat16 gsm[];
    __nv_bfloat16* As = gsm;                      // [GSTAGES][128*40]
    __nv_bfloat16* Bs = gsm + GSTAGES * A_STG;    // [GSTAGES][32*136]

    const int tid  = threadIdx.x;
    const int wid  = tid >> 5;
    const int lane = tid & 31;
    const int wm   = wid >> 1;   // 0..3 -> M offset wm*32
    const int wn   = wid & 1;    // 0..1 -> N offset wn*64

    const int m0 = blockIdx.y * 128;
    const int n0 = blockIdx.x * 128;

    // cp.async chunk mapping: A tile 128x32 = 512 x 16B, B tile 32x128 = 512 x 16B
    // thread handles chunks {tid, tid+256} for each.
    const int ac0_row = tid >> 2, ac0_col = (tid & 3) * 8;
    const int ac1_row = (tid + 256) >> 2, ac1_col = ((tid + 256) & 3) * 8;
    const int bc0_row = tid >> 4, bc0_col = (tid & 15) * 8;
    const int bc1_row = (tid + 256) >> 4, bc1_col = ((tid + 256) & 15) * 8;

    const uint32_t smem_base = (uint32_t)__cvta_generic_to_shared(gsm);
    const uint32_t a_smem0 = smem_base + (uint32_t)((ac0_row * 40 + ac0_col) * 2);
    const uint32_t a_smem1 = smem_base + (uint32_t)((ac1_row * 40 + ac1_col) * 2);
    const uint32_t b_smem_base = smem_base + (uint32_t)(GSTAGES * A_STG * 2);
    const uint32_t b_smem0 = b_smem_base + (uint32_t)((bc0_row * 136 + bc0_col) * 2);
    const uint32_t b_smem1 = b_smem_base + (uint32_t)((bc1_row * 136 + bc1_col) * 2);

    const __nv_bfloat16* Ag0 = A + (size_t)(m0 + ac0_row) * K3 + ac0_col;
    const __nv_bfloat16* Ag1 = A + (size_t)(m0 + ac1_row) * K3 + ac1_col;
    const __nv_bfloat16* Bg0 = B + (size_t)bc0_row * N + n0 + bc0_col;
    const __nv_bfloat16* Bg1 = B + (size_t)bc1_row * N + n0 + bc1_col;

    const int ntile = K3 / 32;

    // prologue: issue first GSTAGES-1 stages
#pragma unroll
    for (int s = 0; s < GSTAGES - 1; s++) {
        const uint32_t ao = (uint32_t)(s * A_STG * 2);
        const uint32_t bo = (uint32_t)(s * B_STG * 2);
        CPASYNC16(a_smem0 + ao, Ag0 + s * 32);
        CPASYNC16(a_smem1 + ao, Ag1 + s * 32);
        CPASYNC16(b_smem0 + bo, Bg0 + (size_t)s * 32 * N);
        CPASYNC16(b_smem1 + bo, Bg1 + (size_t)s * 32 * N);
        CPCOMMIT();
    }

    float acc[2][8][4];
#pragma unroll
    for (int mt = 0; mt < 2; mt++)
#pragma unroll
        for (int nt = 0; nt < 8; nt++)
#pragma unroll
            for (int i = 0; i < 4; i++) acc[mt][nt][i] = 0.f;

    // ldmatrix per-lane offsets
    const uint32_t a_lane_off = (uint32_t)(((lane & 15) * 40 + (lane >> 4) * 8) * 2);
    const uint32_t b_lane_off = (uint32_t)(((lane & 15) * 136 + (lane >> 4) * 8) * 2);

    for (int kt = 0; kt < ntile; kt++) {
        CPWAIT2();            // stage kt complete (<=2 younger groups pending)
        __syncthreads();

        // issue stage kt+GSTAGES-1 (its buffer was consumed at iter kt-1)
        const int knext = kt + GSTAGES - 1;
        if (knext < ntile) {
            const int s = knext & (GSTAGES - 1);
            const uint32_t ao = (uint32_t)(s * A_STG * 2);
            const uint32_t bo = (uint32_t)(s * B_STG * 2);
            CPASYNC16(a_smem0 + ao, Ag0 + knext * 32);
            CPASYNC16(a_smem1 + ao, Ag1 + knext * 32);
            CPASYNC16(b_smem0 + bo, Bg0 + (size_t)knext * 32 * N);
            CPASYNC16(b_smem1 + bo, Bg1 + (size_t)knext * 32 * N);
        }
        CPCOMMIT();           // always commit to keep group accounting fixed

        const int cs = kt & (GSTAGES - 1);
        const uint32_t a_stage = smem_base + (uint32_t)(cs * A_STG * 2);
        const uint32_t b_stage = b_smem_base + (uint32_t)(cs * B_STG * 2);

#pragma unroll
        for (int ks = 0; ks < 2; ks++) {
            const int kk = ks * 16;
            uint32_t af[2][4];
#pragma unroll
            for (int mt = 0; mt < 2; mt++) {
                uint32_t addr = a_stage + a_lane_off +
                                (uint32_t)(((wm * 32 + mt * 16) * 40 + kk) * 2);
                LDMX4(af[mt][0], af[mt][1], af[mt][2], af[mt][3], addr);
            }
            uint32_t bf[4][4];
#pragma unroll
            for (int bt = 0; bt < 4; bt++) {
                uint32_t addr = b_stage + b_lane_off +
                                (uint32_t)((kk * 136 + wn * 64 + bt * 16) * 2);
                LDMX4T(bf[bt][0], bf[bt][1], bf[bt][2], bf[bt][3], addr);
            }
#pragma unroll
            for (int mt = 0; mt < 2; mt++)
#pragma unroll
                for (int nt = 0; nt < 8; nt++) {
                    const int bt = nt >> 1, hf = nt & 1;
                    MMA16816(acc[mt][nt], af[mt], bf[bt][hf * 2], bf[bt][hf * 2 + 1]);
                }
        }
    }

    // epilogue
#pragma unroll
    for (int mt = 0; mt < 2; mt++)
#pragma unroll
        for (int nt = 0; nt < 8; nt++) {
            const int m = m0 + wm * 32 + mt * 16 + (lane >> 2);
            const int n = n0 + wn * 64 + nt * 8 + (lane & 3) * 2;
            *(float2*)(C + (size_t)m * N + n) =
                make_float2(acc[mt][nt][0], acc[mt][nt][1]);
            *(float2*)(C + (size_t)(m + 8) * N + n) =
                make_float2(acc[mt][nt][2], acc[mt][nt][3]);
        }
}

// ---------------------------------------------------------------------------
// RoPE, in place on Q and K. One block per sequence position.
// ---------------------------------------------------------------------------
__global__ void rope_kernel(float* __restrict__ Q, float* __restrict__ K,
                            const int* __restrict__ pos_ids)
{
    const int s = blockIdx.x;
    const float p = (float)pos_ids[s];
    const int total = (NH + NKV) * 64;
    for (int id = threadIdx.x; id < total; id += blockDim.x) {
        const int h = id >> 6;
        const int d = id & 63;
        const float freq = 1.0f / __powf(1000000.0f, (float)d * (1.0f / 64.0f));
        const float t = p * freq;
        float sn, cs;
        __sincosf(t, &sn, &cs);
        float* ptr;
        if (h < NH) ptr = Q + (size_t)s * QKDIM + h * HD;
        else        ptr = K + (size_t)s * KVDIM + (h - NH) * HD;
        const float x1 = ptr[d];
        const float x2 = ptr[d + 64];
        ptr[d]      = x1 * cs - x2 * sn;
        ptr[d + 64] = x1 * sn + x2 * cs;
    }
}

// ---------------------------------------------------------------------------
// Flash-style fp32 attention with smem-resident Q and K tiles (d-major).
// Grid: (S/64 q-blocks, NH heads). Block: 256 threads.  (proven, unchanged)
// ---------------------------------------------------------------------------
#define ATTN_SMEM_FLOATS (128*64 + 128*64 + 64*65 + 16*132 + 3*64)
#define ATTN_SMEM_BYTES  (ATTN_SMEM_FLOATS * 4)

__global__ __launch_bounds__(256) void attn_kernel(
    const float* __restrict__ Q, const float* __restrict__ K,
    const float* __restrict__ V, const float* __restrict__ amask,
    float* __restrict__ ctx)
{
    extern __shared__ float sm[];
    float* Qall = sm;                       // [128][64]
    float* Kall = Qall + 128 * 64;          // [128][64]
    float* Ps   = Kall + 128 * 64;          // [64][65]
    float* Vs   = Ps   + 64 * 65;           // [16][132]
    float* m_s  = Vs   + 16 * 132;          // [64]
    float* l_s  = m_s  + 64;                // [64]
    float* sc_s = l_s  + 64;                // [64]

    const int tid = threadIdx.x;
    const int qb = blockIdx.x;
    const int h  = blockIdx.y;
    const int g  = h >> 2;           // kv head
    const int q0 = qb * 64;
    const int tx = tid & 15;         // 16 cols
    const int ty = tid >> 4;         // 16 rows

    float O[4][8];
#pragma unroll
    for (int r = 0; r < 4; r++)
#pragma unroll
        for (int c = 0; c < 8; c++) O[r][c] = 0.f;

    if (tid < 64) { m_s[tid] = -INFINITY; l_s[tid] = 0.f; }

    const int lm  = tid >> 2;        // 0..63  (row within tile)
    const int ld4 = (tid & 3) * 4;   // 0,4,8,12 (d sub-offset)

    // ---- load full Q tile once, transposed to d-major ----
#pragma unroll
    for (int d0 = 0; d0 < HD; d0 += 16) {
        float4 q4 = *(const float4*)(Q + (size_t)(q0 + lm) * QKDIM + h * HD + d0 + ld4);
        Qall[(d0 + ld4 + 0) * 64 + lm] = q4.x;
        Qall[(d0 + ld4 + 1) * 64 + lm] = q4.y;
        Qall[(d0 + ld4 + 2) * 64 + lm] = q4.z;
        Qall[(d0 + ld4 + 3) * 64 + lm] = q4.w;
    }
    __syncthreads();

    for (int kt = 0; kt <= qb; kt++) {
        const int k0 = kt * 64;

#pragma unroll
        for (int d0 = 0; d0 < HD; d0 += 16) {
            float4 k4 = *(const float4*)(K + (size_t)(k0 + lm) * KVDIM + g * HD + d0 + ld4);
            Kall[(d0 + ld4 + 0) * 64 + lm] = k4.x;
            Kall[(d0 + ld4 + 1) * 64 + lm] = k4.y;
            Kall[(d0 + ld4 + 2) * 64 + lm] = k4.z;
            Kall[(d0 + ld4 + 3) * 64 + lm] = k4.w;
        }
        __syncthreads();

        float s[4][4];
#pragma unroll
        for (int i = 0; i < 4; i++)
#pragma unroll
            for (int j = 0; j < 4; j++) s[i][j] = 0.f;

#pragma unroll 8
        for (int dd = 0; dd < HD; dd++) {
            float4 qa = *(const float4*)(&Qall[dd * 64 + ty * 4]);
            float4 kb = *(const float4*)(&Kall[dd * 64 + tx * 4]);
            s[0][0] = fmaf(qa.x, kb.x, s[0][0]);
            s[0][1] = fmaf(qa.x, kb.y, s[0][1]);
            s[0][2] = fmaf(qa.x, kb.z, s[0][2]);
            s[0][3] = fmaf(qa.x, kb.w, s[0][3]);
            s[1][0] = fmaf(qa.y, kb.x, s[1][0]);
            s[1][1] = fmaf(qa.y, kb.y, s[1][1]);
            s[1][2] = fmaf(qa.y, kb.z, s[1][2]);
            s[1][3] = fmaf(qa.y, kb.w, s[1][3]);
            s[2][0] = fmaf(qa.z, kb.x, s[2][0]);
            s[2][1] = fmaf(qa.z, kb.y, s[2][1]);
            s[2][2] = fmaf(qa.z, kb.z, s[2][2]);
            s[2][3] = fmaf(qa.z, kb.w, s[2][3]);
            s[3][0] = fmaf(qa.w, kb.x, s[3][0]);
            s[3][1] = fmaf(qa.w, kb.y, s[3][1]);
            s[3][2] = fmaf(qa.w, kb.z, s[3][2]);
            s[3][3] = fmaf(qa.w, kb.w, s[3][3]);
        }
#pragma unroll
        for (int i = 0; i < 4; i++)
#pragma unroll
            for (int j = 0; j < 4; j++)
                Ps[(ty * 4 + i) * 65 + tx * 4 + j] = s[i][j] * ATT_SCALE;
        __syncthreads();

        {
            const int row = tid >> 2;
            const int sub = tid & 3;
            const int qg  = q0 + row;
            float pv[16];
            float mloc = -INFINITY;
#pragma unroll
            for (int c2 = 0; c2 < 16; c2++) {
                const int kk = sub * 16 + c2;
                const int kg = k0 + kk;
                float sv = Ps[row * 65 + kk];
                if (kg > qg || amask[kg] <= 0.f) sv = -INFINITY;
                pv[c2] = sv;
                mloc = fmaxf(mloc, sv);
            }
            mloc = fmaxf(mloc, __shfl_xor_sync(0xffffffffu, mloc, 1));
            mloc = fmaxf(mloc, __shfl_xor_sync(0xffffffffu, mloc, 2));
            const float mold = m_s[row];
            const float mnew = fmaxf(mold, mloc);
            float lsum = 0.f;
#pragma unroll
            for (int c2 = 0; c2 < 16; c2++) {
                const float pexp = (pv[c2] == -INFINITY) ? 0.f : __expf(pv[c2] - mnew);
                Ps[row * 65 + sub * 16 + c2] = pexp;
                lsum += pexp;
            }
            lsum += __shfl_xor_sync(0xffffffffu, lsum, 1);
            lsum += __shfl_xor_sync(0xffffffffu, lsum, 2);
            if (sub == 0) {
                const float f = __expf(mold - mnew);
                sc_s[row] = f;
                l_s[row]  = l_s[row] * f + lsum;
                m_s[row]  = mnew;
            }
        }
        __syncthreads();

#pragma unroll
        for (int r = 0; r < 4; r++) {
            const float f = sc_s[ty * 4 + r];
#pragma unroll
            for (int c = 0; c < 8; c++) O[r][c] *= f;
        }
        for (int kk0 = 0; kk0 < 64; kk0 += 16) {
            __syncthreads();
#pragma unroll
            for (int t2 = 0; t2 < 2; t2++) {
                const int idx = tid + t2 * 256;
                const int vr = idx >> 5;
                const int vc = (idx & 31) * 4;
                *(float4*)(&Vs[vr * 132 + vc]) =
                    *(const float4*)(V + (size_t)(k0 + kk0 + vr) * KVDIM + g * HD + vc);
            }
            __syncthreads();
#pragma unroll
            for (int kk = 0; kk < 16; kk++) {
                float pr[4], vv[8];
#pragma unroll
                for (int r = 0; r < 4; r++) pr[r] = Ps[(ty * 4 + r) * 65 + kk0 + kk];
#pragma unroll
                for (int c = 0; c < 8; c++) vv[c] = Vs[kk * 132 + tx * 8 + c];
#pragma unroll
                for (int r = 0; r < 4; r++)
#pragma unroll
                    for (int c = 0; c < 8; c++)
                        O[r][c] = fmaf(pr[r], vv[c], O[r][c]);
            }
        }
        __syncthreads();
    }

#pragma unroll
    for (int r = 0; r < 4; r++) {
        const float inv = 1.0f / l_s[ty * 4 + r];
        float* dst = ctx + (size_t)(q0 + ty * 4 + r) * QKDIM + h * HD + tx * 8;
        float4 v0 = make_float4(O[r][0] * inv, O[r][1] * inv, O[r][2] * inv, O[r][3] * inv);
        float4 v1 = make_float4(O[r][4] * inv, O[r][5] * inv, O[r][6] * inv, O[r][7] * inv);
        *(float4*)(dst + 0) = v0;
        *(float4*)(dst + 4) = v1;
    }
}

// ---------------------------------------------------------------------------
extern "C" void kernel_launch(void* const* d_in, const int* in_sizes, int n_in,
                              void* d_out, int out_size)
{
    const float* hidden = (const float*)d_in[0];
    const float* amask  = (const float*)d_in[1];
    const int*   pos    = (const int*)d_in[2];
    const float* wq     = (const float*)d_in[3];
    const float* wk     = (const float*)d_in[4];
    const float* wv     = (const float*)d_in[5];
    const float* wo     = (const float*)d_in[6];
    float* out = (float*)d_out;

    float *qp, *kp, *vp, *cp;
    __nv_bfloat16 *h3, *w3;
    cudaGetSymbolAddress((void**)&qp, g_q);
    cudaGetSymbolAddress((void**)&kp, g_k);
    cudaGetSymbolAddress((void**)&vp, g_v);
    cudaGetSymbolAddress((void**)&cp, g_ctx);
    cudaGetSymbolAddress((void**)&h3, g_h3);
    cudaGetSymbolAddress((void**)&w3, g_w3);

    cudaFuncSetAttribute(attn_kernel,
                         cudaFuncAttributeMaxDynamicSharedMemorySize,
                         ATTN_SMEM_BYTES);
    cudaFuncSetAttribute(bf16_gemm_kernel,
                         cudaFuncAttributeMaxDynamicSharedMemorySize,
                         GEMM_SMEM_BYTES);

    const int na = S_LEN * D_MODEL / 8;                    // A-side 8-elem blocks
    // hidden -> split A operand
    split3_a_kernel<<<(na + 255) / 256, 256>>>(hidden, h3, na);

    // Q = h3 * wq'
    split3_b_kernel<<<(D_MODEL * (QKDIM / 8) + 255) / 256, 256>>>(wq, w3, D_MODEL, QKDIM);
    bf16_gemm_kernel<<<dim3(QKDIM / 128, S_LEN / 128), 256, GEMM_SMEM_BYTES>>>(h3, w3, qp, QKDIM);
    // K = h3 * wk'
    split3_b_kernel<<<(D_MODEL * (KVDIM / 8) + 255) / 256, 256>>>(wk, w3, D_MODEL, KVDIM);
    bf16_gemm_kernel<<<dim3(KVDIM / 128, S_LEN / 128), 256, GEMM_SMEM_BYTES>>>(h3, w3, kp, KVDIM);
    // V = h3 * wv'
    split3_b_kernel<<<(D_MODEL * (KVDIM / 8) + 255) / 256, 256>>>(wv, w3, D_MODEL, KVDIM);
    bf16_gemm_kernel<<<dim3(KVDIM / 128, S_LEN / 128), 256, GEMM_SMEM_BYTES>>>(h3, w3, vp, KVDIM);

    // RoPE (in place on Q, K)
    rope_kernel<<<S_LEN, 256>>>(qp, kp, pos);
    // Attention
    attn_kernel<<<dim3(S_LEN / 64, NH), 256, ATTN_SMEM_BYTES>>>(qp, kp, vp, amask, cp);

    // out = ctx' * wo'
    split3_a_kernel<<<(na + 255) / 256, 256>>>(cp, h3, na);
    split3_b_kernel<<<(D_MODEL * (QKDIM / 8) + 255) / 256, 256>>>(wo, w3, D_MODEL, QKDIM);
    bf16_gemm_kernel<<<dim3(QKDIM / 128, S_LEN / 128), 256, GEMM_SMEM_BYTES>>>(h3, w3, out, QKDIM);
}